// round 11
// baseline (speedup 1.0000x reference)
#include <cuda_runtime.h>
#include <cuda_bf16.h>

// S4D kernel: K[h,l] = 2*Re( sum_n Ct[h,n] * exp(dtA[h,n]*l) )
// R11 change: __launch_bounds__(256, 2). R9/R10's 8-independent-chain ILP
// structure needs ~110 regs; the default 64-reg cap made ptxas re-serialize
// everything (regs stuck at 58, issue stuck at 54%). Raising the budget to
// 128 regs lets the expressed ILP actually materialize in SASS. Occupancy
// drops to 2 blocks/SM by design; per-warp issue density is the win.

static constexpr int kH     = 1024;
static constexpr int kN2    = 32;
static constexpr int kL     = 4096;
static constexpr int kChunk = 16;
static constexpr int kTPB   = 256;           // kTPB * kChunk == kL
static constexpr int kPairs = kN2 / 2;
static constexpr int kGrp   = 8;             // pairs per ILP group

typedef unsigned long long u64;

__device__ __forceinline__ u64 pk2(float lo, float hi) {
    u64 r; asm("mov.b64 %0, {%1, %2};" : "=l"(r) : "f"(lo), "f"(hi)); return r;
}
__device__ __forceinline__ void upk2(u64 v, float& lo, float& hi) {
    asm("mov.b64 {%0, %1}, %2;" : "=f"(lo), "=f"(hi) : "l"(v));
}
__device__ __forceinline__ u64 fma2(u64 a, u64 b, u64 c) {
    u64 r; asm("fma.rn.f32x2 %0, %1, %2, %3;" : "=l"(r) : "l"(a), "l"(b), "l"(c)); return r;
}
__device__ __forceinline__ u64 mul2(u64 a, u64 b) {
    u64 r; asm("mul.rn.f32x2 %0, %1, %2;" : "=l"(r) : "l"(a), "l"(b)); return r;
}
__device__ __forceinline__ u64 add2(u64 a, u64 b) {
    u64 r; asm("add.rn.f32x2 %0, %1, %2;" : "=l"(r) : "l"(a), "l"(b)); return r;
}
__device__ __forceinline__ float ex2a(float x) {
    float r; asm("ex2.approx.f32 %0, %1;" : "=f"(r) : "f"(x)); return r;
}
__device__ __forceinline__ float sina(float x) {
    float r; asm("sin.approx.f32 %0, %1;" : "=f"(r) : "f"(x)); return r;
}
__device__ __forceinline__ float cosa(float x) {
    float r; asm("cos.approx.f32 %0, %1;" : "=f"(r) : "f"(x)); return r;
}

static __device__ __forceinline__ u64 SGN2() { return 0x8000000080000000ULL; }

// Packed chunk start for a mode pair: u0 = Re(Ct z^{l0}), u1 = Re(Ct z^{l0+1}).
__device__ __forceinline__ void pair_start(
    float4 g1, float4 g2, float4 g3,
    u64 l0f2, u64 nINV2PI2, u64 MAGIC2, u64 nMAGIC2, u64 PI2HI2, u64 PI2MID2,
    u64& u0pk, u64& u1pk)
{
    u64 dreL2 = pk2(g1.x, g1.y);          // dre * log2(e), per mode
    u64 dim2  = pk2(g1.z, g1.w);
    u64 m2 = mul2(dreL2, l0f2);
    float m0, m1; upk2(m2, m0, m1);
    float mag0 = ex2a(m0), mag1 = ex2a(m1);

    u64 p2   = mul2(dim2, l0f2);
    u64 e2   = fma2(dim2, l0f2, p2 ^ SGN2());     // exact residual of dim*l0
    u64 nk2  = fma2(p2, nINV2PI2, MAGIC2);        // MAGIC - p/2pi (rounded on int grid)
    u64 nkf2 = add2(nk2, nMAGIC2);                // = -rint(p/2pi)
    u64 r2   = fma2(nkf2, PI2HI2, p2);
    r2       = add2(r2, fma2(nkf2, PI2MID2, e2));
    float r0, r1; upk2(r2, r0, r1);
    float s0 = sina(r0), c0 = cosa(r0);
    float s1 = sina(r1), c1 = cosa(r1);

    u64 mag2 = pk2(mag0, mag1);
    u64 pr2  = mul2(mag2, pk2(c0, c1));
    u64 pi2  = mul2(mag2, pk2(s0, s1));
    u64 ctr2 = pk2(g2.x, g2.y);
    u64 cti2 = pk2(g2.z, g2.w);
    u64 qr2  = fma2(cti2, pi2 ^ SGN2(), mul2(ctr2, pr2));   // ctr*pr - cti*pi
    u64 qi2  = fma2(cti2, pr2,          mul2(ctr2, pi2));   // ctr*pi + cti*pr
    u64 wr2  = pk2(g3.x, g3.y);
    u64 nwi2 = pk2(g3.z, g3.w);
    u0pk = qr2;
    u1pk = fma2(qi2, nwi2, mul2(qr2, wr2));                  // Re(q*z)
}

struct ModeParams {
    float dreL2, dim, ctr, cti, wr, nwi, a, nb;
};

__device__ __forceinline__ ModeParams mode_setup(float dt, float lAr, float Aim,
                                                 float cr, float ci) {
    const float LOG2E = 1.44269504088896341f;
    ModeParams mp;
    float Are = -__expf(lAr);
    float dre = Are * dt;
    float dim = Aim * dt;
    float er  = __expf(dre);
    float sn, cs;
    __sincosf(dim, &sn, &cs);
    float wr = er * cs, wi = er * sn;
    float e1r = wr - 1.0f, e1i = wi;
    float nr = cr * e1r - ci * e1i;
    float ni = cr * e1i + ci * e1r;
    float a2   = Are * Are + Aim * Aim;
    float inva = 2.0f / a2;                  // factor 2 of output folded in
    mp.ctr   = (nr * Are + ni * Aim) * inva;
    mp.cti   = (ni * Are - nr * Aim) * inva;
    mp.dreL2 = dre * LOG2E;
    mp.dim   = dim;
    mp.wr    = wr;
    mp.nwi   = -wi;
    mp.a     = 2.0f * wr;
    mp.nb    = -(er * er);
    return mp;
}

__global__ __launch_bounds__(kTPB, 2) void s4d_kernel(
    const float* __restrict__ log_dt,
    const float* __restrict__ C_real,
    const float* __restrict__ C_imag,
    const float* __restrict__ log_A_real,
    const float* __restrict__ A_imag,
    float* __restrict__ out)
{
    __shared__ float4 s_g1[kPairs];   // {dreL2_0, dreL2_1, dim_0, dim_1}
    __shared__ float4 s_g2[kPairs];   // {ctr_0,  ctr_1,  cti_0, cti_1}
    __shared__ float4 s_g3[kPairs];   // {wr_0,   wr_1,   nwi_0, nwi_1}
    __shared__ float4 s_g4[kPairs];   // {a_0,    a_1,    nb_0,  nb_1}

    const int h   = blockIdx.x;
    const int tid = threadIdx.x;

    if (tid < kPairs) {
        const int p = tid, n0 = 2 * p, n1 = n0 + 1;
        float dt = __expf(log_dt[h]);
        ModeParams m0 = mode_setup(dt, log_A_real[h * kN2 + n0], A_imag[h * kN2 + n0],
                                   C_real[h * kN2 + n0], C_imag[h * kN2 + n0]);
        ModeParams m1 = mode_setup(dt, log_A_real[h * kN2 + n1], A_imag[h * kN2 + n1],
                                   C_real[h * kN2 + n1], C_imag[h * kN2 + n1]);
        s_g1[p] = make_float4(m0.dreL2, m1.dreL2, m0.dim, m1.dim);
        s_g2[p] = make_float4(m0.ctr,   m1.ctr,   m0.cti, m1.cti);
        s_g3[p] = make_float4(m0.wr,    m1.wr,    m0.nwi, m1.nwi);
        s_g4[p] = make_float4(m0.a,     m1.a,     m0.nb,  m1.nb);
    }
    __syncthreads();

    const float l0f = (float)(tid * kChunk);
    const u64 l0f2 = pk2(l0f, l0f);

    const float INV2PI  = 0.15915494309189535f;
    const float PI2HI   = 6.28318548202514648f;   // fp32(2*pi)
    const float PI2MID  = -1.74845600e-7f;        // 2*pi - PI2HI
    const float MAGIC   = 12582912.0f;            // 1.5 * 2^23
    const u64 nINV2PI2 = pk2(-INV2PI, -INV2PI);
    const u64 MAGIC2   = pk2(MAGIC, MAGIC);
    const u64 nMAGIC2  = pk2(-MAGIC, -MAGIC);
    const u64 PI2HI2   = pk2(PI2HI, PI2HI);
    const u64 PI2MID2  = pk2(PI2MID, PI2MID);

    u64 acc[kChunk];
    #pragma unroll
    for (int j = 0; j < kChunk; j++) acc[j] = 0ULL;   // packed {0.0f, 0.0f}

    #pragma unroll 1
    for (int g = 0; g < kPairs / kGrp; g++) {
        u64 A[kGrp], NB[kGrp], U1[kGrp], W[kGrp];

        // Start kGrp independent chains (MUFU bursts overlap via ILP).
        #pragma unroll
        for (int i = 0; i < kGrp; i++) {
            const int p = g * kGrp + i;
            float4 g4 = s_g4[p];
            A[i]  = pk2(g4.x, g4.y);
            NB[i] = pk2(g4.z, g4.w);
            u64 u0;
            pair_start(s_g1[p], s_g2[p], s_g3[p],
                       l0f2, nINV2PI2, MAGIC2, nMAGIC2, PI2HI2, PI2MID2,
                       u0, U1[i]);
            acc[0] = add2(acc[0], u0);
            acc[1] = add2(acc[1], U1[i]);
            W[i]   = mul2(u0, NB[i]);      // W = (-b)*u_0, lagged product
        }

        // Recurrence: carried chain is ONE fma2 per link (4 cyc); the mul2
        // feeding W has a full link of slack; the acc add is off-chain.
        #pragma unroll
        for (int j = 2; j < kChunk; j++) {
            #pragma unroll
            for (int i = 0; i < kGrp; i++) {
                u64 un = fma2(U1[i], A[i], W[i]);   // u_j = a*u_{j-1} - b*u_{j-2}
                W[i]   = mul2(U1[i], NB[i]);        // (-b)*u_{j-1}, for next link
                acc[j] = add2(acc[j], un);
                U1[i]  = un;
            }
        }
    }

    // Reduce packed halves, store as float4 (64B per thread, aligned).
    float4* outv = (float4*)(out + (size_t)h * kL + (size_t)tid * kChunk);
    #pragma unroll
    for (int v = 0; v < kChunk / 4; v++) {
        float a0, a1, b0, b1, c0, c1, d0, d1;
        upk2(acc[4 * v + 0], a0, a1);
        upk2(acc[4 * v + 1], b0, b1);
        upk2(acc[4 * v + 2], c0, c1);
        upk2(acc[4 * v + 3], d0, d1);
        float4 o;
        o.x = a0 + a1;
        o.y = b0 + b1;
        o.z = c0 + c1;
        o.w = d0 + d1;
        outv[v] = o;
    }
}

extern "C" void kernel_launch(void* const* d_in, const int* in_sizes, int n_in,
                              void* d_out, int out_size) {
    const float* log_dt     = (const float*)d_in[0];
    const float* C_real     = (const float*)d_in[1];
    const float* C_imag     = (const float*)d_in[2];
    const float* log_A_real = (const float*)d_in[3];
    const float* A_imag     = (const float*)d_in[4];
    float* out = (float*)d_out;

    s4d_kernel<<<kH, kTPB>>>(log_dt, C_real, C_imag, log_A_real, A_imag, out);
}